// round 8
// baseline (speedup 1.0000x reference)
#include <cuda_runtime.h>
#include <cstdint>

// ---------------------------------------------------------------------------
// MetaMLP (3-step GraphNet) on GB300 — edge GEMM: smem-staged A + ldmatrix,
// transposed epilogue (coalesced gathers), atomic agg.
// ---------------------------------------------------------------------------

#define D 128
static constexpr int N_NODES  = 50000;
static constexpr int N_EDGES  = 800000;
static constexpr int N_GRAPHS = 16;
static constexpr int OUTW     = 4 * D;           // 512 output cols per row
static constexpr int TILE_E   = 256;             // edges per tile
static constexpr int N_TILES  = N_EDGES / TILE_E; // 3125

typedef unsigned long long u64;

// ------------------------- device scratch (no allocs) ----------------------
__device__ float g_ea  [(size_t)N_EDGES  * D];
__device__ float g_P12 [(size_t)N_NODES  * 2 * D];   // [P1+uW4b+b | P2]
__device__ float g_agg [(size_t)N_NODES  * D];
__device__ float g_u    [N_GRAPHS * D];
__device__ float g_uWn3b[N_GRAPHS * D];
__device__ float g_gsum [N_GRAPHS * D];
__device__ float g_invN [N_NODES];
__device__ float g_invG [N_GRAPHS];

// ------------------------------ helpers ------------------------------------
__device__ __forceinline__ u64 pack2(float a, float b) {
    u64 r; asm("mov.b64 %0, {%1, %2};" : "=l"(r) : "f"(a), "f"(b)); return r;
}
__device__ __forceinline__ float2 unpack2(u64 v) {
    float2 r; asm("mov.b64 {%0, %1}, %2;" : "=f"(r.x), "=f"(r.y) : "l"(v)); return r;
}
__device__ __forceinline__ void ffma2(u64& d, u64 a, u64 b) {
    asm("fma.rn.f32x2 %0, %1, %2, %3;" : "=l"(d) : "l"(a), "l"(b), "l"(d));
}
__device__ __forceinline__ uint32_t cvt_bf16x2(float a, float b) {
    uint32_t r;
    asm("cvt.rn.bf16x2.f32 %0, %1, %2;" : "=r"(r) : "f"(b), "f"(a));
    return r;
}
__device__ __forceinline__ void split2(float x, float y, uint32_t& hi, uint32_t& lo) {
    hi = cvt_bf16x2(x, y);
    float hx = __uint_as_float(hi << 16);
    float hy = __uint_as_float(hi & 0xffff0000u);
    lo = cvt_bf16x2(x - hx, y - hy);
}
__device__ __forceinline__ void mma_bf16(float* d, const uint32_t* a, uint32_t b0, uint32_t b1) {
    asm volatile("mma.sync.aligned.m16n8k16.row.col.f32.bf16.bf16.f32 "
        "{%0,%1,%2,%3}, {%4,%5,%6,%7}, {%8,%9}, {%0,%1,%2,%3};"
        : "+f"(d[0]), "+f"(d[1]), "+f"(d[2]), "+f"(d[3])
        : "r"(a[0]), "r"(a[1]), "r"(a[2]), "r"(a[3]), "r"(b0), "r"(b1));
}
__device__ __forceinline__ void red_add2(float* addr, float x, float y) {
    asm volatile("red.global.add.v2.f32 [%0], {%1, %2};"
                 :: "l"(addr), "f"(x), "f"(y) : "memory");
}
__device__ __forceinline__ uint32_t smem_u32(const void* p) {
    uint32_t a;
    asm("{ .reg .u64 t; cvta.to.shared.u64 t, %1; cvt.u32.u64 %0, t; }" : "=r"(a) : "l"(p));
    return a;
}
__device__ __forceinline__ void ldsm_x4(uint32_t& r0, uint32_t& r1, uint32_t& r2, uint32_t& r3,
                                        uint32_t addr) {
    asm volatile("ldmatrix.sync.aligned.m8n8.x4.shared.b16 {%0,%1,%2,%3}, [%4];"
                 : "=r"(r0), "=r"(r1), "=r"(r2), "=r"(r3) : "r"(addr));
}

// ------------------------------ init (launch 0) -----------------------------
__global__ void init_kernel(const float* __restrict__ x, const float* __restrict__ u,
                            float* __restrict__ out_x, float* __restrict__ out_g) {
    int stride = gridDim.x * blockDim.x;
    int tid0 = blockIdx.x * blockDim.x + threadIdx.x;
    for (int i = tid0; i < N_NODES * D; i += stride) {
        int r = i >> 7, c = i & (D - 1);
        out_x[(size_t)r * OUTW + c] = x[i];
        g_agg[i] = 0.f;
    }
    for (int i = tid0; i < N_GRAPHS * D; i += stride) {
        int r = i >> 7, c = i & (D - 1);
        out_g[(size_t)r * OUTW + c] = u[i];
        g_u[i] = u[i];
    }
    for (int i = tid0; i < N_NODES; i += stride) g_invN[i] = 0.f;
    for (int i = tid0; i < N_GRAPHS; i += stride) g_invG[i] = 0.f;
}

// ------------------------------ hist / finalize ------------------------------
__global__ void hist_kernel(const int* __restrict__ dst, const int* __restrict__ batch) {
    int stride = gridDim.x * blockDim.x;
    int tid0 = blockIdx.x * blockDim.x + threadIdx.x;
    for (int i = tid0; i < N_EDGES; i += stride) atomicAdd(&g_invN[dst[i]], 1.f);
    for (int i = tid0; i < N_NODES; i += stride) atomicAdd(&g_invG[batch[i]], 1.f);
}

__global__ void finalize_counts_kernel() {
    int stride = gridDim.x * blockDim.x;
    int tid0 = blockIdx.x * blockDim.x + threadIdx.x;
    for (int i = tid0; i < N_NODES; i += stride) g_invN[i] = 1.f / fmaxf(g_invN[i], 1.f);
    for (int i = tid0; i < N_GRAPHS; i += stride) g_invG[i] = 1.f / fmaxf(g_invG[i], 1.f);
}

// ----------------------- matvec P1/P2 (512 thr, 16 warps) -------------------
// P1 = X@We1 + (u@We4 + b_edge)[batch]  ;  P2 = X@We2
__global__ void __launch_bounds__(512) matvec_P_kernel(
    const float* __restrict__ X, const float* __restrict__ W_edge,
    const float* __restrict__ b_edge, const int* __restrict__ batch) {
    extern __shared__ float sh[];
    float* sW1 = sh;               // 16384 f
    float* sW2 = sh + 16384;       // 16384 f
    float* sV  = sh + 32768;       // 16 warps * 8 rows * 128 = 16384 f
    float* sGu = sh + 49152;       // 2048 f
    float* sUW = sh + 51200;       // 2048 f
    for (int i = threadIdx.x; i < D * D; i += blockDim.x) {
        sW1[i] = W_edge[i];
        sW2[i] = W_edge[D * D + i];
    }
    for (int i = threadIdx.x; i < N_GRAPHS * D; i += blockDim.x) sGu[i] = g_u[i];
    __syncthreads();
    {
        int j = threadIdx.x & 127, q4 = threadIdx.x >> 7;
        float acc[4];
#pragma unroll
        for (int q = 0; q < 4; q++) acc[q] = 0.f;
        const float* W4 = W_edge + 3 * D * D;
        for (int k = 0; k < D; k++) {
            float w = __ldg(W4 + k * D + j);
#pragma unroll
            for (int q = 0; q < 4; q++)
                acc[q] = fmaf(sGu[(q4 * 4 + q) * D + k], w, acc[q]);
        }
        float bj = __ldg(b_edge + j);
#pragma unroll
        for (int q = 0; q < 4; q++) sUW[(q4 * 4 + q) * D + j] = acc[q] + bj;
    }
    __syncthreads();
    int warp = threadIdx.x >> 5, lane = threadIdx.x & 31;
    float* myV = sV + warp * 8 * D;
    const int groups = N_NODES / 8;
    for (int grp = blockIdx.x * 16 + warp; grp < groups; grp += gridDim.x * 16) {
        int r0 = grp * 8;
#pragma unroll
        for (int e = 0; e < 8; e++) {
            float4 v = *((const float4*)(X + (size_t)(r0 + e) * OUTW) + lane);
            *((float4*)(myV + e * D) + lane) = v;
        }
        __syncwarp();
        u64 a0[8], a1[8], b0[8], b1[8];
#pragma unroll
        for (int e = 0; e < 8; e++) { a0[e] = a1[e] = b0[e] = b1[e] = 0ull; }
        for (int k = 0; k < D; k += 4) {
            ulonglong2 u0 = *((const ulonglong2*)(sW1 + (k + 0) * D) + lane);
            ulonglong2 u1 = *((const ulonglong2*)(sW1 + (k + 1) * D) + lane);
            ulonglong2 u2 = *((const ulonglong2*)(sW1 + (k + 2) * D) + lane);
            ulonglong2 u3 = *((const ulonglong2*)(sW1 + (k + 3) * D) + lane);
            ulonglong2 v0 = *((const ulonglong2*)(sW2 + (k + 0) * D) + lane);
            ulonglong2 v1 = *((const ulonglong2*)(sW2 + (k + 1) * D) + lane);
            ulonglong2 v2 = *((const ulonglong2*)(sW2 + (k + 2) * D) + lane);
            ulonglong2 v3 = *((const ulonglong2*)(sW2 + (k + 3) * D) + lane);
#pragma unroll
            for (int e = 0; e < 8; e++) {
                float4 a = *(const float4*)(myV + e * D + k);
                u64 p;
                p = pack2(a.x, a.x);
                ffma2(a0[e], p, u0.x); ffma2(a1[e], p, u0.y);
                ffma2(b0[e], p, v0.x); ffma2(b1[e], p, v0.y);
                p = pack2(a.y, a.y);
                ffma2(a0[e], p, u1.x); ffma2(a1[e], p, u1.y);
                ffma2(b0[e], p, v1.x); ffma2(b1[e], p, v1.y);
                p = pack2(a.z, a.z);
                ffma2(a0[e], p, u2.x); ffma2(a1[e], p, u2.y);
                ffma2(b0[e], p, v2.x); ffma2(b1[e], p, v2.y);
                p = pack2(a.w, a.w);
                ffma2(a0[e], p, u3.x); ffma2(a1[e], p, u3.y);
                ffma2(b0[e], p, v3.x); ffma2(b1[e], p, v3.y);
            }
        }
#pragma unroll
        for (int e = 0; e < 8; e++) {
            int g = __ldg(batch + r0 + e);
            float4 uv = *((const float4*)(sUW + g * D) + lane);
            float2 r01 = unpack2(a0[e]), r23 = unpack2(a1[e]);
            float2 s01 = unpack2(b0[e]), s23 = unpack2(b1[e]);
            float* base = g_P12 + (size_t)(r0 + e) * (2 * D);
            *((float4*)base + lane) =
                make_float4(r01.x + uv.x, r01.y + uv.y, r23.x + uv.z, r23.y + uv.w);
            *((float4*)(base + D) + lane) = make_float4(s01.x, s01.y, s23.x, s23.y);
        }
        __syncwarp();
    }
}

// ------------------------- edge kernel: mma.sync ----------------------------
// ea' = relu(ea@We3 + P1'[src] + P2[dst]); red-add to agg.
// smem-staged A (bf16 hi/lo, ldmatrix), transposed epilogue via smem.
__global__ void __launch_bounds__(512, 1) edge_mma_kernel(
    int step0, int store_ea, const float* __restrict__ ext_ea,
    const int* __restrict__ src, const int* __restrict__ dst,
    const float* __restrict__ We3) {
    extern __shared__ char smemraw[];
    uint4* sB  = (uint4*)smemraw;                 // 64 KB: [nt16][ks8][lane32]
    char*  sAh = smemraw + 65536;                 // 64 KB bf16 hi (phase 1)
    char*  sAl = smemraw + 131072;                // 64 KB bf16 lo (phase 1)
    char*  sAcc = smemraw + 65536;                // 128 KB f32 acc (phase 2)

    int tid = threadIdx.x;
    // --- pre-pack W fragments (hi/lo split), once per block ---
    for (int i = tid; i < 16 * 8 * 32; i += 512) {
        int lane = i & 31, ks = (i >> 5) & 7, nt = i >> 8;
        int gidw = lane >> 2, tigw = lane & 3;
        int n  = nt * 8 + gidw;
        int k0 = ks * 16 + tigw * 2;
        float w00 = __ldg(We3 + k0 * D + n);
        float w01 = __ldg(We3 + (k0 + 1) * D + n);
        float w10 = __ldg(We3 + (k0 + 8) * D + n);
        float w11 = __ldg(We3 + (k0 + 9) * D + n);
        uint32_t b0h, b0l, b1h, b1l;
        split2(w00, w01, b0h, b0l);
        split2(w10, w11, b1h, b1l);
        sB[i] = make_uint4(b0h, b1h, b0l, b1l);
    }

    int wid = tid >> 5, lane = tid & 31;
    int gid = lane >> 2, tig = lane & 3;
    int wm = wid & 7, wn = wid >> 3;
    const float* ea_in = step0 ? ext_ea : (const float*)g_ea;
    uint32_t sAh_b = smem_u32(sAh), sAl_b = smem_u32(sAl), sAcc_b = smem_u32(sAcc);
    __syncthreads();

    for (int tile = blockIdx.x; tile < N_TILES; tile += gridDim.x) {
        const float* A = ea_in + (size_t)tile * (TILE_E * D);
        // ---- stage A: bf16 hi/lo, swizzled 16B units ----
#pragma unroll
        for (int q = 0; q < 8; q++) {
            int u = tid + q * 512;          // 0..4095 units of 8 floats
            int row = u >> 4, c16 = u & 15;
            const float* p = A + row * D + c16 * 8;
            float4 v0 = __ldcs((const float4*)p);
            float4 v1 = __ldcs((const float4*)(p + 4));
            uint32_t h0, l0, h1, l1, h2, l2, h3, l3;
            split2(v0.x, v0.y, h0, l0); split2(v0.z, v0.w, h1, l1);
            split2(v1.x, v1.y, h2, l2); split2(v1.z, v1.w, h3, l3);
            int sw = row * 256 + ((c16 ^ (row & 7)) << 4);
            *(uint4*)(sAh + sw) = make_uint4(h0, h1, h2, h3);
            *(uint4*)(sAl + sw) = make_uint4(l0, l1, l2, l3);
        }
        __syncthreads();

        // ---- MMA mainloop: ldmatrix A frags + prepacked B frags ----
        float acc[2][8][4];
#pragma unroll
        for (int mt = 0; mt < 2; mt++)
#pragma unroll
            for (int nt = 0; nt < 8; nt++)
#pragma unroll
                for (int q = 0; q < 4; q++) acc[mt][nt][q] = 0.f;

#pragma unroll
        for (int ks = 0; ks < 8; ks++) {
            uint32_t ah[2][4], al[2][4];
#pragma unroll
            for (int mt = 0; mt < 2; mt++) {
                int rowA = wm * 32 + mt * 16 + (lane & 15);
                int unit = ks * 2 + (lane >> 4);
                uint32_t off = rowA * 256 + (((unit ^ (rowA & 7)) & 15) << 4);
                ldsm_x4(ah[mt][0], ah[mt][1], ah[mt][2], ah[mt][3], sAh_b + off);
                ldsm_x4(al[mt][0], al[mt][1], al[mt][2], al[mt][3], sAl_b + off);
            }
#pragma unroll
            for (int nt = 0; nt < 8; nt++) {
                uint4 b = sB[((wn * 8 + nt) * 8 + ks) * 32 + lane];
#pragma unroll
                for (int mt = 0; mt < 2; mt++) {
                    mma_bf16(acc[mt][nt], ah[mt], b.x, b.y);   // Ahi*Whi
                    mma_bf16(acc[mt][nt], ah[mt], b.z, b.w);   // Ahi*Wlo
                    mma_bf16(acc[mt][nt], al[mt], b.x, b.y);   // Alo*Whi
                }
            }
        }
        __syncthreads();   // all LDSM done before overwriting with Sacc

        // ---- dump acc to smem (f32, swizzled 16B units) ----
#pragma unroll
        for (int mt = 0; mt < 2; mt++)
#pragma unroll
            for (int h = 0; h < 2; h++) {
                int row = wm * 32 + mt * 16 + h * 8 + gid;
#pragma unroll
                for (int nt = 0; nt < 8; nt++) {
                    int col = wn * 64 + nt * 8 + tig * 2;
                    int u = col >> 2;
                    uint32_t off = row * 512 + (((u ^ (row & 7)) & 31) << 4) + ((col << 2) & 15);
                    *(float2*)(sAcc + off) =
                        make_float2(acc[mt][nt][h * 2], acc[mt][nt][h * 2 + 1]);
                }
            }
        __syncthreads();

        // ---- transposed epilogue: 8-lane groups per edge, 128B chunks ----
        int le = lane >> 3;      // edge within warp group (0..3)
        int lc = lane & 7;       // 16B unit within 128B chunk
#pragma unroll
        for (int pass = 0; pass < 4; pass++) {
            int rloc = pass * 64 + wid * 4 + le;
            int r = tile * TILE_E + rloc;
            int s = __ldg(src + r), d = __ldg(dst + r);
            const float4* p1b = (const float4*)(g_P12 + (size_t)s * 256);
            const float4* p2b = (const float4*)(g_P12 + (size_t)d * 256 + 128);
            float* eo = g_ea + (size_t)r * D;
            float* ao = g_agg + (size_t)d * D;
#pragma unroll
            for (int ch = 0; ch < 4; ch++) {
                int u = ch * 8 + lc;     // 0..31
                uint32_t off = rloc * 512 + (((u ^ (rloc & 7)) & 31) << 4);
                float4 a = *(float4*)(sAcc + off);
                float4 p1 = __ldg(p1b + u);
                float4 p2 = __ldg(p2b + u);
                float4 rr;
                rr.x = fmaxf(a.x + p1.x + p2.x, 0.f);
                rr.y = fmaxf(a.y + p1.y + p2.y, 0.f);
                rr.z = fmaxf(a.z + p1.z + p2.z, 0.f);
                rr.w = fmaxf(a.w + p1.w + p2.w, 0.f);
                if (store_ea) __stcs((float4*)(eo + u * 4), rr);
                red_add2(ao + u * 4, rr.x, rr.y);
                red_add2(ao + u * 4 + 2, rr.z, rr.w);
            }
        }
        __syncthreads();   // before next tile's staging overwrites sAcc/sAh
    }
}

// --------------------------- prep2 (uWn3b + gsum=0) -------------------------
__global__ void prep2_kernel(const float* __restrict__ W_node,
                             const float* __restrict__ b_node) {
    int g = blockIdx.x, j = threadIdx.x;
    __shared__ float su[D];
    su[j] = g_u[g * D + j];
    __syncthreads();
    const float* W3 = W_node + 2 * D * D;
    float acc = b_node[j];
#pragma unroll 8
    for (int k = 0; k < D; k++) acc = fmaf(su[k], W3[k * D + j], acc);
    g_uWn3b[g * D + j] = acc;
    g_gsum[g * D + j] = 0.f;
}

// ------------------------- node kernel (512 thr, 16 warps) ------------------
__global__ void __launch_bounds__(512) node_kernel(
    const float* __restrict__ Xin, float* __restrict__ Xout,
    const int* __restrict__ batch, const float* __restrict__ W_node) {
    extern __shared__ float sh[];
    float* sW = sh;
    float* sU = sh + 2 * D * D;
    float* sV = sU + N_GRAPHS * D;
    for (int i = threadIdx.x; i < 2 * D * D; i += blockDim.x) sW[i] = W_node[i];
    for (int i = threadIdx.x; i < N_GRAPHS * D; i += blockDim.x) sU[i] = g_uWn3b[i];
    __syncthreads();
    int warp = threadIdx.x >> 5, lane = threadIdx.x & 31;
    float* myV = sV + warp * 4 * (2 * D);
    const int groups = N_NODES / 4;
    for (int grp = blockIdx.x * 16 + warp; grp < groups; grp += gridDim.x * 16) {
        int r0 = grp * 4;
#pragma unroll
        for (int e = 0; e < 4; e++) {
            int row = r0 + e;
            float4 xv = *((const float4*)(Xin + (size_t)row * OUTW) + lane);
            *((float4*)(myV + e * 2 * D) + lane) = xv;
            float inv = __ldg(&g_invN[row]);
            float4 av = *((const float4*)(g_agg + (size_t)row * D) + lane);
            *((float4*)(g_agg + (size_t)row * D) + lane) = make_float4(0.f, 0.f, 0.f, 0.f);
            av.x *= inv; av.y *= inv; av.z *= inv; av.w *= inv;
            *((float4*)(myV + e * 2 * D + D) + lane) = av;
        }
        __syncwarp();
        u64 acc0[4], acc1[4];
#pragma unroll
        for (int e = 0; e < 4; e++) { acc0[e] = 0ull; acc1[e] = 0ull; }
        for (int k = 0; k < 2 * D; k += 4) {
            ulonglong2 w0 = *((const ulonglong2*)(sW + (k + 0) * D) + lane);
            ulonglong2 w1 = *((const ulonglong2*)(sW + (k + 1) * D) + lane);
            ulonglong2 w2 = *((const ulonglong2*)(sW + (k + 2) * D) + lane);
            ulonglong2 w3 = *((const ulonglong2*)(sW + (k + 3) * D) + lane);
#pragma unroll
            for (int e = 0; e < 4; e++) {
                float4 a = *(const float4*)(myV + e * 2 * D + k);
                u64 p;
                p = pack2(a.x, a.x); ffma2(acc0[e], p, w0.x); ffma2(acc1[e], p, w0.y);
                p = pack2(a.y, a.y); ffma2(acc0[e], p, w1.x); ffma2(acc1[e], p, w1.y);
                p = pack2(a.z, a.z); ffma2(acc0[e], p, w2.x); ffma2(acc1[e], p, w2.y);
                p = pack2(a.w, a.w); ffma2(acc0[e], p, w3.x); ffma2(acc1[e], p, w3.y);
            }
        }
#pragma unroll
        for (int e = 0; e < 4; e++) {
            int row = r0 + e;
            int g = __ldg(batch + row);
            float4 ub = *((const float4*)(sU + g * D) + lane);
            float2 c01 = unpack2(acc0[e]), c23 = unpack2(acc1[e]);
            float4 r;
            r.x = fmaxf(c01.x + ub.x, 0.f);
            r.y = fmaxf(c01.y + ub.y, 0.f);
            r.z = fmaxf(c23.x + ub.z, 0.f);
            r.w = fmaxf(c23.y + ub.w, 0.f);
            *((float4*)(Xout + (size_t)row * OUTW) + lane) = r;
            atomicAdd((float4*)(g_gsum + g * D) + lane, r);
        }
        __syncwarp();
    }
}

// ------------------------------ global kernel ------------------------------
__global__ void global_kernel(const float* __restrict__ W_glob,
                              const float* __restrict__ b_glob,
                              float* __restrict__ out_g) {
    int g = blockIdx.x;
    int j = threadIdx.x;
    __shared__ float su[D], sm[D];
    su[j] = g_u[g * D + j];
    sm[j] = g_gsum[g * D + j] * g_invG[g];
    __syncthreads();
    float acc = b_glob[j];
#pragma unroll 4
    for (int k = 0; k < D; k++) acc = fmaf(su[k], W_glob[k * D + j], acc);
#pragma unroll 4
    for (int k = 0; k < D; k++) acc = fmaf(sm[k], W_glob[(D + k) * D + j], acc);
    float r = fmaxf(acc, 0.f);
    out_g[(size_t)g * OUTW + j] = r;
    g_u[g * D + j] = r;
}

// --------------------------------- launch ----------------------------------
extern "C" void kernel_launch(void* const* d_in, const int* in_sizes, int n_in,
                              void* d_out, int out_size) {
    const float* x      = (const float*)d_in[0];
    const int*   ei     = (const int*)d_in[1];
    const float* ea     = (const float*)d_in[2];
    const float* u      = (const float*)d_in[3];
    const int*   batch  = (const int*)d_in[4];
    const float* W_edge = (const float*)d_in[5];
    const float* b_edge = (const float*)d_in[6];
    const float* W_node = (const float*)d_in[7];
    const float* b_node = (const float*)d_in[8];
    const float* W_glob = (const float*)d_in[9];
    const float* b_glob = (const float*)d_in[10];

    const int* src = ei;
    const int* dstp = ei + N_EDGES;

    float* out   = (float*)d_out;
    float* out_x = out;                            // 50000 x 512
    float* out_g = out + (size_t)N_NODES * OUTW;   // 16 x 512

    const int MV_SMEM   = 53248 * 4;               // 208 KB
    const int EDGE_SMEM = 196608;                  // 192 KB (sB 64 + A/acc 128)
    const int NODE_SMEM = (2 * D * D + N_GRAPHS * D + 16 * 4 * 2 * D) * 4;  // 200 KB

    cudaFuncSetAttribute(matvec_P_kernel, cudaFuncAttributeMaxDynamicSharedMemorySize, MV_SMEM);
    cudaFuncSetAttribute(edge_mma_kernel, cudaFuncAttributeMaxDynamicSharedMemorySize, EDGE_SMEM);
    cudaFuncSetAttribute(node_kernel,     cudaFuncAttributeMaxDynamicSharedMemorySize, NODE_SMEM);

    // launch order: index 3 (ncu capture point) = edge_mma_kernel
    init_kernel<<<2048, 256>>>(x, u, out_x, out_g);                        // 0
    matvec_P_kernel<<<148, 512, MV_SMEM>>>(out_x, W_edge, b_edge, batch);  // 1 (t=0)
    hist_kernel<<<1024, 256>>>(dstp, batch);                               // 2
    edge_mma_kernel<<<148, 512, EDGE_SMEM>>>(1, 1, ea, src, dstp,          // 3 PROFILED
                                             W_edge + 2 * D * D);
    finalize_counts_kernel<<<256, 256>>>();                                // 4

    for (int t = 0; t < 3; t++) {
        const float* Xt = out_x + t * D;
        float*       Xn = out_x + (t + 1) * D;

        prep2_kernel<<<16, 128>>>(W_node, b_node);
        node_kernel<<<148, 512, NODE_SMEM>>>(Xt, Xn, batch, W_node);
        global_kernel<<<16, 128>>>(W_glob, b_glob, out_g + (t + 1) * D);

        if (t < 2) {
            matvec_P_kernel<<<148, 512, MV_SMEM>>>(Xn, W_edge, b_edge, batch);
            edge_mma_kernel<<<148, 512, EDGE_SMEM>>>(0, (t + 1) < 2 ? 1 : 0, ea,
                                                     src, dstp, W_edge + 2 * D * D);
        }
    }
}